// round 7
// baseline (speedup 1.0000x reference)
#include <cuda_runtime.h>
#include <cstdint>

// Problem shapes (fixed per reference setup_inputs)
#define BB 32
#define HH 1024
#define WW 1024
#define TH 512
#define TW 512
#define SS 256

// Tiling: 8 output rows x 512 output cols per tile
#define PT_ROWS 8
#define TT_ROWS 6            // target rows needed per tile (4 + halo 2)
#define STCOLS 264           // staged target cols (4 halo + 256 + 4 halo)
#define TSLOTS 66            // float4 slots per target row
#define NTILES 8192          // 32 b * 128 rowblocks * 2 halves
#define GRID 296             // 148 SMs * 2 CTAs, persistent

__device__ double g_img_sum = 0.0;
__device__ double g_stn_sum = 0.0;
__device__ unsigned int g_count = 0;

__device__ __forceinline__ void cp_async16(void* smem_dst, const void* gmem_src) {
    uint32_t s = (uint32_t)__cvta_generic_to_shared(smem_dst);
    asm volatile("cp.async.cg.shared.global [%0], [%1], 16;" :: "r"(s), "l"(gmem_src));
}
__device__ __forceinline__ void cp_commit() { asm volatile("cp.async.commit_group;"); }
template <int N>
__device__ __forceinline__ void cp_wait() {
    asm volatile("cp.async.wait_group %0;" :: "n"(N));
}

// Persistent fused kernel. 296 blocks, each processes ~28 tiles with a
// double-buffered cp.async pipeline (prefetch tile t+1 during compute of t).
// Tile T: b = T>>8, rowblock = (T&255)>>1, half = T&1.
__global__ __launch_bounds__(256, 2) void fused_kernel(const float* __restrict__ pred,
                                                       const float* __restrict__ tgt,
                                                       const int* __restrict__ pos,
                                                       const float* __restrict__ run,
                                                       float* __restrict__ out) {
    __shared__ float sp[2][PT_ROWS][512];      // pred staging, 32 KB
    __shared__ float st[2][TT_ROWS][STCOLS];   // target staging, 12.4 KB
    __shared__ float wsum[8];
    __shared__ float wsum2[8];

    const int tid = threadIdx.x;
    const int bid = blockIdx.x;

    // ---- Station loss (blocks 0..31, one batch each, one station/thread) ----
    float stn_val = 0.f;
    if (bid < BB) {
        int idx = bid * SS + tid;
        int px = pos[2 * idx];       // column
        int py = pos[2 * idx + 1];   // row
        const float* pb0 = pred + (size_t)bid * HH * WW;
        float sum = 0.f;
        int cnt = 0;
#pragma unroll
        for (int dy = -1; dy <= 1; ++dy) {
            int y = py + dy;
            if ((unsigned)y < (unsigned)HH) {
#pragma unroll
                for (int dx = -1; dx <= 1; ++dx) {
                    int x = px + dx;
                    if ((unsigned)x < (unsigned)WW) {
                        sum += pb0[(size_t)y * WW + x];
                        cnt++;
                    }
                }
            }
        }
        float d = sum / (float)cnt - run[idx];
        stn_val = d * d;
    }

    // ---- Tile prefetch helper (cp.async into buffer `buf`) ----
    auto issue_tile = [&](int T, int buf) {
        int b    = T >> 8;
        int rem  = T & 255;
        int rb   = rem >> 1;          // rowblock 0..127
        int h    = rem & 1;
        int ybase = rb * PT_ROWS;
        int kbase = rb * 4 - 1;
        int cb    = 256 * h - 4;
        const float* pbase = pred + ((size_t)b * HH + ybase) * WW + 512 * h;
#pragma unroll
        for (int i = 0; i < 4; ++i) {
            int idx = tid + i * 256;          // 0..1023 float4 slots
            int r   = idx >> 7;               // 0..7
            int c4  = (idx & 127) << 2;       // 0..508
            cp_async16(&sp[buf][r][c4], pbase + (size_t)r * WW + c4);
        }
        const float* tb = tgt + (size_t)b * TH * TW;
#pragma unroll
        for (int i = 0; i < 2; ++i) {
            int idx = tid + i * 256;          // 0..511
            if (idx < TT_ROWS * TSLOTS) {     // 396 slots
                int r = idx / TSLOTS;
                int s = idx - r * TSLOTS;
                int k = kbase + r;
                k = k < 0 ? 0 : (k > TH - 1 ? TH - 1 : k);
                int c = cb + 4 * s;
                c = c < 0 ? 0 : (c > TW - 4 ? TW - 4 : c);  // edge slots never read
                cp_async16(&st[buf][r][4 * s], tb + (size_t)k * TW + c);
            }
        }
    };

    float acc = 0.f;

    // ---- Pipelined tile loop ----
    if (bid < NTILES) {                  // always true (GRID < NTILES)
        issue_tile(bid, 0);
        cp_commit();
        int i = 0;
        for (int T = bid; T < NTILES; T += GRID, ++i) {
            int buf = i & 1;
            int Tn = T + GRID;
            if (Tn < NTILES) {
                issue_tile(Tn, buf ^ 1);
                cp_commit();
                cp_wait<1>();
            } else {
                cp_wait<0>();
            }
            __syncthreads();

            int h = T & 1;
            // smem col indices for target blend (global col kcol = 256h + tid)
            int jm = tid + 3; if (h == 0 && tid == 0)   jm = 4;
            int jp = tid + 5; if (h == 1 && tid == 255) jp = 259;
            const int j = tid + 4;

            float am = st[buf][0][jm], a0 = st[buf][0][j], ap = st[buf][0][jp];
            float bm = st[buf][1][jm], b0 = st[buf][1][j], bp = st[buf][1][jp];

#pragma unroll
            for (int p = 0; p < 4; ++p) {
                float cm = st[buf][p + 2][jm];
                float c0 = st[buf][p + 2][j];
                float cp_ = st[buf][p + 2][jp];

                // even output row 2p: vertical 0.25*row(p) + 0.75*row(p+1)
                float2 pv = *(const float2*)&sp[buf][2 * p][2 * tid];
                float vm = 0.25f * am + 0.75f * bm;
                float v0 = 0.25f * a0 + 0.75f * b0;
                float vp = 0.25f * ap + 0.75f * bp;
                float d;
                d = pv.x - (0.25f * vm + 0.75f * v0); acc = fmaf(d, d, acc);
                d = pv.y - (0.75f * v0 + 0.25f * vp); acc = fmaf(d, d, acc);

                // odd output row 2p+1: vertical 0.75*row(p+1) + 0.25*row(p+2)
                pv = *(const float2*)&sp[buf][2 * p + 1][2 * tid];
                vm = 0.75f * bm + 0.25f * cm;
                v0 = 0.75f * b0 + 0.25f * c0;
                vp = 0.75f * bp + 0.25f * cp_;
                d = pv.x - (0.25f * vm + 0.75f * v0); acc = fmaf(d, d, acc);
                d = pv.y - (0.75f * v0 + 0.25f * vp); acc = fmaf(d, d, acc);

                am = bm; a0 = b0; ap = bp;
                bm = cm; b0 = c0; bp = cp_;
            }
            __syncthreads();   // all reads of buf done before it is refilled
        }
    }

    // ---- Final block reductions (once per block) ----
#pragma unroll
    for (int o = 16; o > 0; o >>= 1) {
        acc     += __shfl_xor_sync(0xffffffffu, acc, o);
        stn_val += __shfl_xor_sync(0xffffffffu, stn_val, o);
    }
    int lane = tid & 31, wid = tid >> 5;
    if (lane == 0) { wsum[wid] = acc; wsum2[wid] = stn_val; }
    __syncthreads();

    if (tid == 0) {
        float s = 0.f, s2 = 0.f;
#pragma unroll
        for (int i = 0; i < 8; ++i) { s += wsum[i]; s2 += wsum2[i]; }
        atomicAdd(&g_img_sum, (double)s);
        if (bid < BB) atomicAdd(&g_stn_sum, (double)s2);
        __threadfence();
        unsigned int old = atomicAdd(&g_count, 1u);
        if (old == GRID - 1) {
            double img = atomicAdd(&g_img_sum, 0.0) / (double)((size_t)BB * HH * WW);
            double stn = atomicAdd(&g_stn_sum, 0.0) / (double)(BB * SS);
            out[0] = (float)(img + 0.5 * stn);  // IMAGE_W=1.0, STATION_W=0.5
            out[1] = (float)img;
            out[2] = (float)stn;
            g_img_sum = 0.0;
            g_stn_sum = 0.0;
            __threadfence();
            g_count = 0u;
        }
    }
}

extern "C" void kernel_launch(void* const* d_in, const int* in_sizes, int n_in,
                              void* d_out, int out_size) {
    const float* pred = (const float*)d_in[0];   // (32,1,1024,1024) f32
    const float* tgt  = (const float*)d_in[1];   // (32,1,512,512) f32
    const int*   pos  = (const int*)d_in[2];     // (32,256,2) i32
    const float* run  = (const float*)d_in[3];   // (32,256) f32
    float* out = (float*)d_out;

    fused_kernel<<<GRID, 256>>>(pred, tgt, pos, run, out);
}